// round 13
// baseline (speedup 1.0000x reference)
#include <cuda_runtime.h>
#include <cuda_fp16.h>
#include <cstdint>

#define NW        1024
#define WIN_ELEMS (256*192)
#define LDH       200

__device__ __align__(16) __half g_q[NW*WIN_ELEMS];
__device__ __align__(16) __half g_k[NW*WIN_ELEMS];
__device__ __align__(16) __half g_v[NW*WIN_ELEMS];
__device__ __align__(16) __half g_lepe[NW*WIN_ELEMS];
__device__ __align__(16) __half g_wh[147456];   // fp16 wqkv (110592) then wout (36864)

__device__ __forceinline__ unsigned smem_u32(const void* ptr)
{
    return (unsigned)__cvta_generic_to_shared(ptr);
}

__device__ __forceinline__ void ldsm4(unsigned* r, unsigned a)
{
    asm volatile("ldmatrix.sync.aligned.m8n8.x4.shared.b16 {%0,%1,%2,%3}, [%4];" : "=r"(r[0]), "=r"(r[1]), "=r"(r[2]), "=r"(r[3]) : "r"(a));
}

__device__ __forceinline__ void ldsm4t(unsigned* r, unsigned a)
{
    asm volatile("ldmatrix.sync.aligned.m8n8.x4.trans.shared.b16 {%0,%1,%2,%3}, [%4];" : "=r"(r[0]), "=r"(r[1]), "=r"(r[2]), "=r"(r[3]) : "r"(a));
}

__device__ __forceinline__ void mma16816(float* d, const unsigned* a, const unsigned* b)
{
    asm volatile("mma.sync.aligned.m16n8k16.row.col.f32.f16.f16.f32 {%0,%1,%2,%3},{%4,%5,%6,%7},{%8,%9},{%0,%1,%2,%3};" : "+f"(d[0]), "+f"(d[1]), "+f"(d[2]), "+f"(d[3]) : "r"(a[0]), "r"(a[1]), "r"(a[2]), "r"(a[3]), "r"(b[0]), "r"(b[1]));
}

__device__ __forceinline__ void cpa16(unsigned dst, const void* src)
{
    asm volatile("cp.async.cg.shared.global [%0], [%1], 16;" :: "r"(dst), "l"(src));
}

#define CPA_COMMIT() asm volatile("cp.async.commit_group;")
#define CPA_WAIT(n)  asm volatile("cp.async.wait_group %0;" :: "n"(n))

// ---------------------------------------------------------------------------
// K0: one-shot weight conversion fp32 -> fp16 (wqkv then wout).
// ---------------------------------------------------------------------------
__global__ __launch_bounds__(256) void convw_kernel(const float* __restrict__ wqkv, const float* __restrict__ wout)
{
    int i = blockIdx.x*256 + threadIdx.x;
    if (i < 55296) {
        ((__half2*)g_wh)[i] = __floats2half2_rn(wqkv[2*i], wqkv[2*i+1]);
    } else if (i < 73728) {
        int j = i - 55296;
        ((__half2*)g_wh)[i] = __floats2half2_rn(wout[2*j], wout[2*j+1]);
    }
}

// ---------------------------------------------------------------------------
// K1: QKV projection (HMMA) + fused LePE tail. CTA = half window (128 rows).
// 256 threads, 8 warps, warp tile 32x32 (grid 4M x 2N). (R11 version)
// ---------------------------------------------------------------------------
__global__ __launch_bounds__(256) void qkv_kernel(const float* __restrict__ x, const float* __restrict__ bqkv,
                                                  const float* __restrict__ wpe, const float* __restrict__ bpe)
{
    extern __shared__ __half sh_qkv[];
    __half* As    = sh_qkv;
    float*  s_wpe = (float*)((char*)sh_qkv + 102400);
    float*  s_bpe = s_wpe + 864;

    const int tid  = threadIdx.x;
    const int warp = tid >> 5;
    const int lane = tid & 31;
    const int hw   = blockIdx.x;
    const int win  = hw >> 1;
    const int t0   = (hw & 1) * 128;
    const int cbase= (hw & 1) * 96;
    const int bb   = win >> 8;
    const int hy   = (win >> 4) & 15;
    const int wx   = win & 15;
    const int winbase = bb*12582912 + hy*786432 + wx*3072;
    const int grp  = lane >> 2;
    const int t2   = (lane & 3) * 2;
    const int wm   = (warp >> 1) * 32;
    const int wn   = (warp & 1) * 32;

    #pragma unroll
    for (int bt = 0; bt < 2; bt++) {
        const __half* wsrc = g_wh + bt*64*192;
        unsigned bbase = smem_u32((char*)sh_qkv + 51200 + bt*25600);
        #pragma unroll
        for (int it = 0; it < 6; it++) {
            int i   = tid + it*256;
            int row = i / 24;
            int cc  = (i % 24) * 8;
            cpa16(bbase + row*(LDH*2) + cc*2, wsrc + row*192 + cc);
        }
        CPA_COMMIT();
    }

    #pragma unroll
    for (int it = 0; it < 4; it++) {
        int i = tid + it*256;
        if (i < 864) { s_wpe[i] = wpe[cbase*9 + i]; }
    }
    if (tid < 96) { s_bpe[tid] = bpe[cbase + tid]; }

    #pragma unroll
    for (int it = 0; it < 24; it++) {
        int i   = tid + it*256;
        int row = i / 48;
        int c   = (i % 48) * 4;
        int gtok = t0 + row;
        const float* src = x + winbase + (gtok>>4)*49152 + (gtok&15)*192 + c;
        float4 av = *(const float4*)src;
        __half2* dp = (__half2*)(As + row*LDH + c);
        dp[0] = __floats2half2_rn(av.x, av.y);
        dp[1] = __floats2half2_rn(av.z, av.w);
    }

    for (int nt = 0; nt < 9; nt++) {
        if (nt >= 7) { CPA_WAIT(0); } else { CPA_WAIT(1); }
        __syncthreads();

        const __half* Bs = (const __half*)((char*)sh_qkv + 51200 + (nt & 1)*25600);

        float acc[2][4][4];
        for (int i = 0; i < 2; i++) {
            for (int j = 0; j < 4; j++) {
                for (int q = 0; q < 4; q++) { acc[i][j][q] = 0.f; }
            }
        }

        #pragma unroll
        for (int k0 = 0; k0 < 192; k0 += 16) {
            unsigned afr[2][4];
            #pragma unroll
            for (int mi = 0; mi < 2; mi++) {
                unsigned aaddr = smem_u32(As + (wm + mi*16 + (lane&15))*LDH + k0 + (lane>>4)*8);
                ldsm4(afr[mi], aaddr);
            }
            #pragma unroll
            for (int nb = 0; nb < 2; nb++) {
                unsigned bfr[4];
                unsigned baddr = smem_u32(Bs + (wn + nb*16 + (lane&7) + ((lane>>4)<<3))*LDH + k0 + ((lane>>3)&1)*8);
                ldsm4(bfr, baddr);
                #pragma unroll
                for (int mi = 0; mi < 2; mi++) {
                    mma16816(acc[mi][nb*2],   afr[mi], bfr);
                    mma16816(acc[mi][nb*2+1], afr[mi], bfr+2);
                }
            }
        }
        __syncthreads();

        if (nt + 2 < 9) {
            const __half* wsrc = g_wh + (nt+2)*64*192;
            unsigned bbase = smem_u32((char*)sh_qkv + 51200 + (nt & 1)*25600);
            #pragma unroll
            for (int it = 0; it < 6; it++) {
                int i   = tid + it*256;
                int row = i / 24;
                int cc  = (i % 24) * 8;
                cpa16(bbase + row*(LDH*2) + cc*2, wsrc + row*192 + cc);
            }
        }
        CPA_COMMIT();

        __half* obuf = g_v;
        if (nt < 3) { obuf = g_q; }
        else if (nt < 6) { obuf = g_k; }
        const int c0 = (nt % 3) * 64;
        const float* bp = bqkv + nt*64;

        #pragma unroll
        for (int mi = 0; mi < 2; mi++) {
            #pragma unroll
            for (int rh = 0; rh < 2; rh++) {
                int tok = t0 + wm + mi*16 + grp + rh*8;
                __half* orow = obuf + win*WIN_ELEMS + tok*192 + c0;
                #pragma unroll
                for (int nj = 0; nj < 4; nj++) {
                    int cl = wn + nj*8 + t2;
                    float v0 = acc[mi][nj][rh*2+0] + bp[cl];
                    float v1 = acc[mi][nj][rh*2+1] + bp[cl+1];
                    *(__half2*)(orow + cl) = __floats2half2_rn(v0, v1);
                }
            }
        }
    }

    __syncthreads();
    __half* vflat = As;
    const __half* vsrc = g_v + win*WIN_ELEMS + t0*192;
    #pragma unroll
    for (int it = 0; it < 12; it++) {
        int i = tid + it*256;
        ((uint4*)vflat)[i] = ((const uint4*)vsrc)[i];
    }
    __syncthreads();

    __half* ldst = g_lepe + win*WIN_ELEMS + t0*192;
    #pragma unroll 4
    for (int it = 0; it < 96; it++) {
        int f  = tid + it*256;
        int ci = f >> 8;
        int p  = f & 255;
        int iy = p >> 4;
        int ix = p & 15;
        float s = s_bpe[ci];
        const float* wv = s_wpe + ci*9;
        const __half* img = vflat + ci*256;
        #pragma unroll
        for (int dy = -1; dy <= 1; dy++) {
            #pragma unroll
            for (int dx = -1; dx <= 1; dx++) {
                int jy = iy + dy;
                int jx = ix + dx;
                if (jy >= 0 && jy < 16 && jx >= 0 && jx < 16) {
                    s += __half2float(img[jy*16 + jx]) * wv[(dy+1)*3 + (dx+1)];
                }
            }
        }
        ldst[f] = __float2half(s);
    }
}

// ---------------------------------------------------------------------------
// K3: register-resident fused attention + projection. 128 threads, 4 warps,
// CTA = 64 q rows, 2 CTAs/SM. Warp owns 16 q rows x all 256 kv cols.
// smem (102400 B): Qs[0,25600) Kbuf[25600,76800) Vbuf[76800,102400)
//                  Wt overlays [0,76800) after S phase.
// cp.async groups: C1=Q+K0  C2=V0  C3=K1  C4=Wt  C5=V1  C6=V2  C7=V3
// ---------------------------------------------------------------------------
__global__ __launch_bounds__(128, 2) void attn_kernel(const float* __restrict__ bout, float* __restrict__ out)
{
    extern __shared__ char sh_attn[];
    __half* Qs   = (__half*)sh_attn;
    __half* Kbuf = (__half*)(sh_attn + 25600);
    __half* Vbuf = (__half*)(sh_attn + 76800);
    __half* Wt   = (__half*)sh_attn;

    const int tid  = threadIdx.x;
    const int warp = tid >> 5;
    const int lane = tid & 31;
    const int win  = blockIdx.x >> 2;
    const int t0   = (blockIdx.x & 3) * 64;
    const int grp  = lane >> 2;
    const int t2   = (lane & 3) * 2;
    const int wm   = warp * 16;

    const __half* qg = g_q + win*WIN_ELEMS + t0*192;
    const __half* kg = g_k + win*WIN_ELEMS;
    const __half* vg = g_v + win*WIN_ELEMS;

    // C1: Q (64 rows) + K chunk0 (128 rows)
    #pragma unroll
    for (int it = 0; it < 12; it++) {
        int i   = tid + it*128;
        int row = i / 24;
        int cc  = (i % 24) * 8;
        cpa16(smem_u32(Qs + row*LDH + cc), qg + row*192 + cc);
    }
    #pragma unroll
    for (int it = 0; it < 24; it++) {
        int i   = tid + it*128;
        int row = i / 24;
        int cc  = (i % 24) * 8;
        cpa16(smem_u32(Kbuf + row*LDH + cc), kg + row*192 + cc);
    }
    CPA_COMMIT();

    // C2: V chunk0 (64 rows)
    #pragma unroll
    for (int it = 0; it < 12; it++) {
        int i   = tid + it*128;
        int row = i / 24;
        int cc  = (i % 24) * 8;
        cpa16(smem_u32(Vbuf + row*LDH + cc), vg + row*192 + cc);
    }
    CPA_COMMIT();

    CPA_WAIT(1);        // Q + K0 ready; V0 may pend
    __syncthreads();

    // Q fragments (held for both K chunks)
    unsigned qa[48];
    #pragma unroll
    for (int ks = 0; ks < 12; ks++) {
        unsigned aaddr = smem_u32(Qs + (wm + (lane&15))*LDH + ks*16 + (lane>>4)*8);
        ldsm4(qa + ks*4, aaddr);
    }

    float acc[32][4];
    for (int j = 0; j < 32; j++) {
        for (int q = 0; q < 4; q++) { acc[j][q] = 0.f; }
    }

    // S chunk 0 (kv cols 0..127)
    #pragma unroll
    for (int ks = 0; ks < 12; ks++) {
        #pragma unroll
        for (int njp = 0; njp < 8; njp++) {
            unsigned bfr[4];
            unsigned baddr = smem_u32(Kbuf + (njp*16 + (lane&7) + ((lane>>4)<<3))*LDH + ks*16 + ((lane>>3)&1)*8);
            ldsm4(bfr, baddr);
            mma16816(acc[njp*2],   qa + ks*4, bfr);
            mma16816(acc[njp*2+1], qa + ks*4, bfr+2);
        }
    }
    __syncthreads();   // Kbuf consumed

    // C3: K chunk1 into Kbuf
    #pragma unroll
    for (int it = 0; it < 24; it++) {
        int i   = tid + it*128;
        int row = i / 24;
        int cc  = (i % 24) * 8;
        cpa16(smem_u32(Kbuf + row*LDH + cc), kg + (128+row)*192 + cc);
    }
    CPA_COMMIT();
    CPA_WAIT(0);       // V0 + K1 complete
    __syncthreads();

    // S chunk 1 (kv cols 128..255)
    #pragma unroll
    for (int ks = 0; ks < 12; ks++) {
        #pragma unroll
        for (int njp = 0; njp < 8; njp++) {
            unsigned bfr[4];
            unsigned baddr = smem_u32(Kbuf + (njp*16 + (lane&7) + ((lane>>4)<<3))*LDH + ks*16 + ((lane>>3)&1)*8);
            ldsm4(bfr, baddr);
            mma16816(acc[16 + njp*2],   qa + ks*4, bfr);
            mma16816(acc[16 + njp*2+1], qa + ks*4, bfr+2);
        }
    }
    __syncthreads();   // Kbuf + Qs dead -> Wt may overlay

    // C4: Wt (192 rows) overlays [0, 76800)
    #pragma unroll
    for (int it = 0; it < 36; it++) {
        int i   = tid + it*128;
        int row = i / 24;
        int cc  = (i % 24) * 8;
        cpa16(smem_u32(Wt + row*LDH + cc), g_wh + 110592 + row*192 + cc);
    }
    CPA_COMMIT();

    // ---- softmax in registers (quad shuffles only) ----
    const float scale = 0.07216878364870323f;
    float mx0 = -1e30f;
    float mx1 = -1e30f;
    #pragma unroll
    for (int nj = 0; nj < 32; nj++) {
        acc[nj][0] *= scale; acc[nj][1] *= scale;
        acc[nj][2] *= scale; acc[nj][3] *= scale;
        mx0 = fmaxf(mx0, fmaxf(acc[nj][0], acc[nj][1]));
        mx1 = fmaxf(mx1, fmaxf(acc[nj][2], acc[nj][3]));
    }
    mx0 = fmaxf(mx0, __shfl_xor_sync(0xffffffffu, mx0, 1));
    mx0 = fmaxf(mx0, __shfl_xor_sync(0xffffffffu, mx0, 2));
    mx1 = fmaxf(mx1, __shfl_xor_sync(0xffffffffu, mx1, 1));
    mx1 = fmaxf(mx1, __shfl_xor_sync(0xffffffffu, mx1, 2));

    unsigned ph[64];
    float sum0 = 0.f;
    float sum1 = 0.f;
    #pragma unroll
    for (int nj = 0; nj < 32; nj++) {
        float e0 = __expf(acc[nj][0] - mx0);
        float e1 = __expf(acc[nj][1] - mx0);
        float e2 = __expf(acc[nj][2] - mx1);
        float e3 = __expf(acc[nj][3] - mx1);
        sum0 += e0 + e1;
        sum1 += e2 + e3;
        __half2 h01 = __floats2half2_rn(e0, e1);
        __half2 h23 = __floats2half2_rn(e2, e3);
        ph[nj*2+0] = *(unsigned*)&h01;
        ph[nj*2+1] = *(unsigned*)&h23;
    }
    sum0 += __shfl_xor_sync(0xffffffffu, sum0, 1);
    sum0 += __shfl_xor_sync(0xffffffffu, sum0, 2);
    sum1 += __shfl_xor_sync(0xffffffffu, sum1, 1);
    sum1 += __shfl_xor_sync(0xffffffffu, sum1, 2);
    const float inv0 = 1.f / sum0;
    const float inv1 = 1.f / sum1;

    // ---- O = P V : 4 V chunks of 64, single buffer ----
    float oacc[24][4];
    for (int j = 0; j < 24; j++) {
        for (int q = 0; q < 4; q++) { oacc[j][q] = 0.f; }
    }

    #pragma unroll
    for (int vc = 0; vc < 4; vc++) {
        #pragma unroll
        for (int kq = 0; kq < 4; kq++) {
            int kt = vc*4 + kq;
            #pragma unroll
            for (int g12 = 0; g12 < 12; g12++) {
                unsigned bfr[4];
                unsigned baddr = smem_u32(Vbuf + (kq*16 + (lane&7) + ((lane>>3)&1)*8)*LDH + g12*16 + (lane>>4)*8);
                ldsm4t(bfr, baddr);
                mma16816(oacc[g12*2],   ph + 4*kt, bfr);
                mma16816(oacc[g12*2+1], ph + 4*kt, bfr+2);
            }
        }
        if (vc < 3) {
            __syncthreads();   // Vbuf consumed by all warps
            #pragma unroll
            for (int it = 0; it < 12; it++) {
                int i   = tid + it*128;
                int row = i / 24;
                int cc  = (i % 24) * 8;
                cpa16(smem_u32(Vbuf + row*LDH + cc), vg + ((vc+1)*64+row)*192 + cc);
            }
            CPA_COMMIT();
            CPA_WAIT(0);       // (also drains Wt on first pass)
            __syncthreads();
        }
    }
    __syncthreads();           // ensure Wt visible to all (C4 waited above)

    // ---- finalize O: inv + lepe; repack as proj A-fragments ----
    const __half* lw = g_lepe + win*WIN_ELEMS + t0*192;
    unsigned oh[48];
    #pragma unroll
    for (int nj = 0; nj < 24; nj++) {
        int c = nj*8 + t2;
        __half2 l0 = *(const __half2*)(lw + (wm + grp)*192 + c);
        __half2 l1 = *(const __half2*)(lw + (wm + grp + 8)*192 + c);
        float2 lp0 = __half22float2(l0);
        float2 lp1 = __half22float2(l1);
        float v0 = oacc[nj][0]*inv0 + lp0.x;
        float v1 = oacc[nj][1]*inv0 + lp0.y;
        float v2 = oacc[nj][2]*inv1 + lp1.x;
        float v3 = oacc[nj][3]*inv1 + lp1.y;
        __half2 h01 = __floats2half2_rn(v0, v1);
        __half2 h23 = __floats2half2_rn(v2, v3);
        oh[nj*2+0] = *(unsigned*)&h01;
        oh[nj*2+1] = *(unsigned*)&h23;
    }

    // ---- fused projection: O (regs) @ wout (smem), scatter to out ----
    float pacc[24][4];
    for (int j = 0; j < 24; j++) {
        for (int q = 0; q < 4; q++) { pacc[j][q] = 0.f; }
    }

    #pragma unroll
    for (int ks = 0; ks < 12; ks++) {
        #pragma unroll
        for (int nj2 = 0; nj2 < 12; nj2++) {
            unsigned bfr[4];
            unsigned baddr = smem_u32(Wt + (nj2*16 + (lane&7) + ((lane>>4)<<3))*LDH + ks*16 + ((lane>>3)&1)*8);
            ldsm4(bfr, baddr);
            mma16816(pacc[nj2*2],   oh + 4*ks, bfr);
            mma16816(pacc[nj2*2+1], oh + 4*ks, bfr+2);
        }
    }

    const int bb = win >> 8;
    const int hy = (win >> 4) & 15;
    const int wx = win & 15;
    #pragma unroll
    for (int rh = 0; rh < 2; rh++) {
        int t  = t0 + wm + grp + rh*8;
        int ty = t >> 4;
        int tx = t & 15;
        int base = bb*12582912 + hy*786432 + ty*49152 + wx*3072 + tx*192;
        #pragma unroll
        for (int nj = 0; nj < 24; nj++) {
            int c = nj*8 + t2;
            float2 o2;
            o2.x = pacc[nj][rh*2+0] + bout[c];
            o2.y = pacc[nj][rh*2+1] + bout[c+1];
            *(float2*)(out + base + c) = o2;
        }
    }
}

// ---------------------------------------------------------------------------
extern "C" void kernel_launch(void* const* d_in, const int* in_sizes, int n_in,
                              void* d_out, int out_size)
{
    const float* x    = (const float*)d_in[0];
    const float* wqkv = (const float*)d_in[1];
    const float* bqkv = (const float*)d_in[2];
    const float* wpe  = (const float*)d_in[3];
    const float* bpe  = (const float*)d_in[4];
    const float* wout = (const float*)d_in[5];
    const float* bout = (const float*)d_in[6];
    float* out = (float*)d_out;

    const int sm_qkv  = 106240;
    const int sm_attn = 102400;
    cudaFuncSetAttribute(qkv_kernel,  cudaFuncAttributeMaxDynamicSharedMemorySize, sm_qkv);
    cudaFuncSetAttribute(attn_kernel, cudaFuncAttributeMaxDynamicSharedMemorySize, sm_attn);

    convw_kernel<<<288, 256>>>(wqkv, wout);
    qkv_kernel <<<2048, 256, sm_qkv>>>(x, bqkv, wpe, bpe);
    attn_kernel<<<4096, 128, sm_attn>>>(bout, out);
}

// round 14
// speedup vs baseline: 1.0032x; 1.0032x over previous
#include <cuda_runtime.h>
#include <cuda_fp16.h>
#include <cstdint>

#define NW        1024
#define WIN_ELEMS (256*192)
#define LDH       200

__device__ __align__(16) __half g_q[NW*WIN_ELEMS];
__device__ __align__(16) __half g_k[NW*WIN_ELEMS];
__device__ __align__(16) __half g_v[NW*WIN_ELEMS];
__device__ __align__(16) __half g_lepe[NW*WIN_ELEMS];
__device__ __align__(16) __half g_wh[147456];   // fp16 wqkv (110592) then wout (36864)

__device__ __forceinline__ unsigned smem_u32(const void* ptr)
{
    return (unsigned)__cvta_generic_to_shared(ptr);
}

__device__ __forceinline__ void ldsm4(unsigned* r, unsigned a)
{
    asm volatile("ldmatrix.sync.aligned.m8n8.x4.shared.b16 {%0,%1,%2,%3}, [%4];" : "=r"(r[0]), "=r"(r[1]), "=r"(r[2]), "=r"(r[3]) : "r"(a));
}

__device__ __forceinline__ void ldsm4t(unsigned* r, unsigned a)
{
    asm volatile("ldmatrix.sync.aligned.m8n8.x4.trans.shared.b16 {%0,%1,%2,%3}, [%4];" : "=r"(r[0]), "=r"(r[1]), "=r"(r[2]), "=r"(r[3]) : "r"(a));
}

__device__ __forceinline__ void mma16816(float* d, const unsigned* a, const unsigned* b)
{
    asm volatile("mma.sync.aligned.m16n8k16.row.col.f32.f16.f16.f32 {%0,%1,%2,%3},{%4,%5,%6,%7},{%8,%9},{%0,%1,%2,%3};" : "+f"(d[0]), "+f"(d[1]), "+f"(d[2]), "+f"(d[3]) : "r"(a[0]), "r"(a[1]), "r"(a[2]), "r"(a[3]), "r"(b[0]), "r"(b[1]));
}

__device__ __forceinline__ void cpa16(unsigned dst, const void* src)
{
    asm volatile("cp.async.cg.shared.global [%0], [%1], 16;" :: "r"(dst), "l"(src));
}

#define CPA_COMMIT() asm volatile("cp.async.commit_group;")
#define CPA_WAIT(n)  asm volatile("cp.async.wait_group %0;" :: "n"(n))

// ---------------------------------------------------------------------------
// K0: one-shot weight conversion fp32 -> fp16 (wqkv then wout).
// ---------------------------------------------------------------------------
__global__ __launch_bounds__(256) void convw_kernel(const float* __restrict__ wqkv, const float* __restrict__ wout)
{
    int i = blockIdx.x*256 + threadIdx.x;
    if (i < 55296) {
        ((__half2*)g_wh)[i] = __floats2half2_rn(wqkv[2*i], wqkv[2*i+1]);
    } else if (i < 73728) {
        int j = i - 55296;
        ((__half2*)g_wh)[i] = __floats2half2_rn(wout[2*j], wout[2*j+1]);
    }
}

// ---------------------------------------------------------------------------
// K1: QKV projection (HMMA) + fused LePE tail. CTA = half window (128 rows).
// 256 threads, 8 warps, warp tile 32x32 (grid 4M x 2N). (R11 version)
// ---------------------------------------------------------------------------
__global__ __launch_bounds__(256) void qkv_kernel(const float* __restrict__ x, const float* __restrict__ bqkv,
                                                  const float* __restrict__ wpe, const float* __restrict__ bpe)
{
    extern __shared__ __half sh_qkv[];
    __half* As    = sh_qkv;
    float*  s_wpe = (float*)((char*)sh_qkv + 102400);
    float*  s_bpe = s_wpe + 864;

    const int tid  = threadIdx.x;
    const int warp = tid >> 5;
    const int lane = tid & 31;
    const int hw   = blockIdx.x;
    const int win  = hw >> 1;
    const int t0   = (hw & 1) * 128;
    const int cbase= (hw & 1) * 96;
    const int bb   = win >> 8;
    const int hy   = (win >> 4) & 15;
    const int wx   = win & 15;
    const int winbase = bb*12582912 + hy*786432 + wx*3072;
    const int grp  = lane >> 2;
    const int t2   = (lane & 3) * 2;
    const int wm   = (warp >> 1) * 32;
    const int wn   = (warp & 1) * 32;

    #pragma unroll
    for (int bt = 0; bt < 2; bt++) {
        const __half* wsrc = g_wh + bt*64*192;
        unsigned bbase = smem_u32((char*)sh_qkv + 51200 + bt*25600);
        #pragma unroll
        for (int it = 0; it < 6; it++) {
            int i   = tid + it*256;
            int row = i / 24;
            int cc  = (i % 24) * 8;
            cpa16(bbase + row*(LDH*2) + cc*2, wsrc + row*192 + cc);
        }
        CPA_COMMIT();
    }

    #pragma unroll
    for (int it = 0; it < 4; it++) {
        int i = tid + it*256;
        if (i < 864) { s_wpe[i] = wpe[cbase*9 + i]; }
    }
    if (tid < 96) { s_bpe[tid] = bpe[cbase + tid]; }

    #pragma unroll
    for (int it = 0; it < 24; it++) {
        int i   = tid + it*256;
        int row = i / 48;
        int c   = (i % 48) * 4;
        int gtok = t0 + row;
        const float* src = x + winbase + (gtok>>4)*49152 + (gtok&15)*192 + c;
        float4 av = *(const float4*)src;
        __half2* dp = (__half2*)(As + row*LDH + c);
        dp[0] = __floats2half2_rn(av.x, av.y);
        dp[1] = __floats2half2_rn(av.z, av.w);
    }

    for (int nt = 0; nt < 9; nt++) {
        if (nt >= 7) { CPA_WAIT(0); } else { CPA_WAIT(1); }
        __syncthreads();

        const __half* Bs = (const __half*)((char*)sh_qkv + 51200 + (nt & 1)*25600);

        float acc[2][4][4];
        for (int i = 0; i < 2; i++) {
            for (int j = 0; j < 4; j++) {
                for (int q = 0; q < 4; q++) { acc[i][j][q] = 0.f; }
            }
        }

        #pragma unroll
        for (int k0 = 0; k0 < 192; k0 += 16) {
            unsigned afr[2][4];
            #pragma unroll
            for (int mi = 0; mi < 2; mi++) {
                unsigned aaddr = smem_u32(As + (wm + mi*16 + (lane&15))*LDH + k0 + (lane>>4)*8);
                ldsm4(afr[mi], aaddr);
            }
            #pragma unroll
            for (int nb = 0; nb < 2; nb++) {
                unsigned bfr[4];
                unsigned baddr = smem_u32(Bs + (wn + nb*16 + (lane&7) + ((lane>>4)<<3))*LDH + k0 + ((lane>>3)&1)*8);
                ldsm4(bfr, baddr);
                #pragma unroll
                for (int mi = 0; mi < 2; mi++) {
                    mma16816(acc[mi][nb*2],   afr[mi], bfr);
                    mma16816(acc[mi][nb*2+1], afr[mi], bfr+2);
                }
            }
        }
        __syncthreads();

        if (nt + 2 < 9) {
            const __half* wsrc = g_wh + (nt+2)*64*192;
            unsigned bbase = smem_u32((char*)sh_qkv + 51200 + (nt & 1)*25600);
            #pragma unroll
            for (int it = 0; it < 6; it++) {
                int i   = tid + it*256;
                int row = i / 24;
                int cc  = (i % 24) * 8;
                cpa16(bbase + row*(LDH*2) + cc*2, wsrc + row*192 + cc);
            }
        }
        CPA_COMMIT();

        __half* obuf = g_v;
        if (nt < 3) { obuf = g_q; }
        else if (nt < 6) { obuf = g_k; }
        const int c0 = (nt % 3) * 64;
        const float* bp = bqkv + nt*64;

        #pragma unroll
        for (int mi = 0; mi < 2; mi++) {
            #pragma unroll
            for (int rh = 0; rh < 2; rh++) {
                int tok = t0 + wm + mi*16 + grp + rh*8;
                __half* orow = obuf + win*WIN_ELEMS + tok*192 + c0;
                #pragma unroll
                for (int nj = 0; nj < 4; nj++) {
                    int cl = wn + nj*8 + t2;
                    float v0 = acc[mi][nj][rh*2+0] + bp[cl];
                    float v1 = acc[mi][nj][rh*2+1] + bp[cl+1];
                    *(__half2*)(orow + cl) = __floats2half2_rn(v0, v1);
                }
            }
        }
    }

    __syncthreads();
    __half* vflat = As;
    const __half* vsrc = g_v + win*WIN_ELEMS + t0*192;
    #pragma unroll
    for (int it = 0; it < 12; it++) {
        int i = tid + it*256;
        ((uint4*)vflat)[i] = ((const uint4*)vsrc)[i];
    }
    __syncthreads();

    __half* ldst = g_lepe + win*WIN_ELEMS + t0*192;
    #pragma unroll 4
    for (int it = 0; it < 96; it++) {
        int f  = tid + it*256;
        int ci = f >> 8;
        int p  = f & 255;
        int iy = p >> 4;
        int ix = p & 15;
        float s = s_bpe[ci];
        const float* wv = s_wpe + ci*9;
        const __half* img = vflat + ci*256;
        #pragma unroll
        for (int dy = -1; dy <= 1; dy++) {
            #pragma unroll
            for (int dx = -1; dx <= 1; dx++) {
                int jy = iy + dy;
                int jx = ix + dx;
                if (jy >= 0 && jy < 16 && jx >= 0 && jx < 16) {
                    s += __half2float(img[jy*16 + jx]) * wv[(dy+1)*3 + (dx+1)];
                }
            }
        }
        ldst[f] = __float2half(s);
    }
}

// ---------------------------------------------------------------------------
// K3: register-resident fused attention + projection. 256 threads, 8 warps.
// R11 structure; CHANGE: Q A-fragments loaded per k-step (no qa[48] preload)
// to cut S-phase register pressure and let ptxas pipeline the B ldsm batch.
// ---------------------------------------------------------------------------
__global__ __launch_bounds__(256) void attn_kernel(const float* __restrict__ bout, float* __restrict__ out)
{
    extern __shared__ char sh_attn[];
    __half* Qs    = (__half*)sh_attn;
    __half* Kfull = (__half*)(sh_attn + 51200);
    __half* Wt    = (__half*)(sh_attn + 51200);

    const int tid  = threadIdx.x;
    const int warp = tid >> 5;
    const int lane = tid & 31;
    const int win  = blockIdx.x >> 1;
    const int t0   = (blockIdx.x & 1) * 128;
    const int grp  = lane >> 2;
    const int t2   = (lane & 3) * 2;
    const int wm   = warp * 16;

    const __half* qg = g_q + win*WIN_ELEMS + t0*192;
    const __half* kg = g_k + win*WIN_ELEMS;
    const __half* vg = g_v + win*WIN_ELEMS;

    #pragma unroll
    for (int it = 0; it < 12; it++) {
        int i   = tid + it*256;
        int row = i / 24;
        int cc  = (i % 24) * 8;
        cpa16(smem_u32(Qs + row*LDH + cc), qg + row*192 + cc);
    }
    #pragma unroll
    for (int it = 0; it < 24; it++) {
        int i   = tid + it*256;
        int row = i / 24;
        int cc  = (i % 24) * 8;
        cpa16(smem_u32(Kfull + row*LDH + cc), kg + row*192 + cc);
    }
    CPA_COMMIT();

    #pragma unroll
    for (int vc0 = 0; vc0 < 2; vc0++) {
        unsigned vb = smem_u32(sh_attn + 153600 + vc0*25600);
        #pragma unroll
        for (int it = 0; it < 6; it++) {
            int i   = tid + it*256;
            int row = i / 24;
            int cc  = (i % 24) * 8;
            cpa16(vb + row*(LDH*2) + cc*2, vg + (vc0*64+row)*192 + cc);
        }
        CPA_COMMIT();
    }

    CPA_WAIT(2);
    __syncthreads();

    // ---- S = Q K^T : A-fragment loaded per k-step (low reg pressure) ----
    float acc[32][4];
    for (int j = 0; j < 32; j++) {
        for (int q = 0; q < 4; q++) { acc[j][q] = 0.f; }
    }

    #pragma unroll
    for (int ks = 0; ks < 12; ks++) {
        unsigned afr[4];
        unsigned aaddr = smem_u32(Qs + (wm + (lane&15))*LDH + ks*16 + (lane>>4)*8);
        ldsm4(afr, aaddr);
        #pragma unroll
        for (int njp = 0; njp < 16; njp++) {
            unsigned bfr[4];
            unsigned baddr = smem_u32(Kfull + (njp*16 + (lane&7) + ((lane>>4)<<3))*LDH + ks*16 + ((lane>>3)&1)*8);
            ldsm4(bfr, baddr);
            mma16816(acc[njp*2],   afr, bfr);
            mma16816(acc[njp*2+1], afr, bfr+2);
        }
    }
    __syncthreads();

    #pragma unroll
    for (int it = 0; it < 18; it++) {
        int i   = tid + it*256;
        int row = i / 24;
        int cc  = (i % 24) * 8;
        cpa16(smem_u32(Wt + row*LDH + cc), g_wh + 110592 + row*192 + cc);
    }
    CPA_COMMIT();

    const float scale = 0.07216878364870323f;
    float mx0 = -1e30f;
    float mx1 = -1e30f;
    #pragma unroll
    for (int nj = 0; nj < 32; nj++) {
        acc[nj][0] *= scale; acc[nj][1] *= scale;
        acc[nj][2] *= scale; acc[nj][3] *= scale;
        mx0 = fmaxf(mx0, fmaxf(acc[nj][0], acc[nj][1]));
        mx1 = fmaxf(mx1, fmaxf(acc[nj][2], acc[nj][3]));
    }
    mx0 = fmaxf(mx0, __shfl_xor_sync(0xffffffffu, mx0, 1));
    mx0 = fmaxf(mx0, __shfl_xor_sync(0xffffffffu, mx0, 2));
    mx1 = fmaxf(mx1, __shfl_xor_sync(0xffffffffu, mx1, 1));
    mx1 = fmaxf(mx1, __shfl_xor_sync(0xffffffffu, mx1, 2));

    unsigned ph[64];
    float sum0 = 0.f;
    float sum1 = 0.f;
    #pragma unroll
    for (int nj = 0; nj < 32; nj++) {
        float e0 = __expf(acc[nj][0] - mx0);
        float e1 = __expf(acc[nj][1] - mx0);
        float e2 = __expf(acc[nj][2] - mx1);
        float e3 = __expf(acc[nj][3] - mx1);
        sum0 += e0 + e1;
        sum1 += e2 + e3;
        __half2 h01 = __floats2half2_rn(e0, e1);
        __half2 h23 = __floats2half2_rn(e2, e3);
        ph[nj*2+0] = *(unsigned*)&h01;
        ph[nj*2+1] = *(unsigned*)&h23;
    }
    sum0 += __shfl_xor_sync(0xffffffffu, sum0, 1);
    sum0 += __shfl_xor_sync(0xffffffffu, sum0, 2);
    sum1 += __shfl_xor_sync(0xffffffffu, sum1, 1);
    sum1 += __shfl_xor_sync(0xffffffffu, sum1, 2);
    const float inv0 = 1.f / sum0;
    const float inv1 = 1.f / sum1;

    float oacc[24][4];
    for (int j = 0; j < 24; j++) {
        for (int q = 0; q < 4; q++) { oacc[j][q] = 0.f; }
    }

    #pragma unroll
    for (int cc4 = 0; cc4 < 4; cc4++) {
        if (cc4 == 0) { CPA_WAIT(2); }
        else if (cc4 == 1) { CPA_WAIT(2); }
        else if (cc4 == 2) { CPA_WAIT(1); }
        else { CPA_WAIT(0); }
        __syncthreads();

        const __half* Vb = (const __half*)(sh_attn + 153600 + (cc4 & 1)*25600);

        #pragma unroll
        for (int kq = 0; kq < 4; kq++) {
            int kt = cc4*4 + kq;
            #pragma unroll
            for (int g12 = 0; g12 < 12; g12++) {
                unsigned bfr[4];
                unsigned baddr = smem_u32(Vb + (kq*16 + (lane&7) + ((lane>>3)&1)*8)*LDH + g12*16 + (lane>>4)*8);
                ldsm4t(bfr, baddr);
                mma16816(oacc[g12*2],   ph + 4*kt, bfr);
                mma16816(oacc[g12*2+1], ph + 4*kt, bfr+2);
            }
        }
        __syncthreads();

        if (cc4 < 2) {
            unsigned vb = smem_u32(sh_attn + 153600 + (cc4 & 1)*25600);
            #pragma unroll
            for (int it = 0; it < 6; it++) {
                int i   = tid + it*256;
                int row = i / 24;
                int cc  = (i % 24) * 8;
                cpa16(vb + row*(LDH*2) + cc*2, vg + ((cc4+2)*64+row)*192 + cc);
            }
            CPA_COMMIT();
        }
    }

    const __half* lw = g_lepe + win*WIN_ELEMS + t0*192;
    unsigned oh[48];
    #pragma unroll
    for (int nj = 0; nj < 24; nj++) {
        int c = nj*8 + t2;
        __half2 l0 = *(const __half2*)(lw + (wm + grp)*192 + c);
        __half2 l1 = *(const __half2*)(lw + (wm + grp + 8)*192 + c);
        float2 lp0 = __half22float2(l0);
        float2 lp1 = __half22float2(l1);
        float v0 = oacc[nj][0]*inv0 + lp0.x;
        float v1 = oacc[nj][1]*inv0 + lp0.y;
        float v2 = oacc[nj][2]*inv1 + lp1.x;
        float v3 = oacc[nj][3]*inv1 + lp1.y;
        __half2 h01 = __floats2half2_rn(v0, v1);
        __half2 h23 = __floats2half2_rn(v2, v3);
        oh[nj*2+0] = *(unsigned*)&h01;
        oh[nj*2+1] = *(unsigned*)&h23;
    }

    float pacc[24][4];
    for (int j = 0; j < 24; j++) {
        for (int q = 0; q < 4; q++) { pacc[j][q] = 0.f; }
    }

    #pragma unroll
    for (int ks = 0; ks < 12; ks++) {
        #pragma unroll
        for (int nj2 = 0; nj2 < 12; nj2++) {
            unsigned bfr[4];
            unsigned baddr = smem_u32(Wt + (nj2*16 + (lane&7) + ((lane>>4)<<3))*LDH + ks*16 + ((lane>>3)&1)*8);
            ldsm4(bfr, baddr);
            mma16816(pacc[nj2*2],   oh + 4*ks, bfr);
            mma16816(pacc[nj2*2+1], oh + 4*ks, bfr+2);
        }
    }

    const int bb = win >> 8;
    const int hy = (win >> 4) & 15;
    const int wx = win & 15;
    #pragma unroll
    for (int rh = 0; rh < 2; rh++) {
        int t  = t0 + wm + grp + rh*8;
        int ty = t >> 4;
        int tx = t & 15;
        int base = bb*12582912 + hy*786432 + ty*49152 + wx*3072 + tx*192;
        #pragma unroll
        for (int nj = 0; nj < 24; nj++) {
            int c = nj*8 + t2;
            float2 o2;
            o2.x = pacc[nj][rh*2+0] + bout[c];
            o2.y = pacc[nj][rh*2+1] + bout[c+1];
            *(float2*)(out + base + c) = o2;
        }
    }
}

// ---------------------------------------------------------------------------
extern "C" void kernel_launch(void* const* d_in, const int* in_sizes, int n_in,
                              void* d_out, int out_size)
{
    const float* x    = (const float*)d_in[0];
    const float* wqkv = (const float*)d_in[1];
    const float* bqkv = (const float*)d_in[2];
    const float* wpe  = (const float*)d_in[3];
    const float* bpe  = (const float*)d_in[4];
    const float* wout = (const float*)d_in[5];
    const float* bout = (const float*)d_in[6];
    float* out = (float*)d_out;

    const int sm_qkv  = 106240;
    const int sm_attn = 204800;
    cudaFuncSetAttribute(qkv_kernel,  cudaFuncAttributeMaxDynamicSharedMemorySize, sm_qkv);
    cudaFuncSetAttribute(attn_kernel, cudaFuncAttributeMaxDynamicSharedMemorySize, sm_attn);

    convw_kernel<<<288, 256>>>(wqkv, wout);
    qkv_kernel <<<2048, 256, sm_qkv>>>(x, bqkv, wpe, bpe);
    attn_kernel<<<2048, 256, sm_attn>>>(bout, out);
}

// round 15
// speedup vs baseline: 1.0211x; 1.0179x over previous
#include <cuda_runtime.h>
#include <cuda_fp16.h>
#include <cstdint>

#define NW        1024
#define WIN_ELEMS (256*192)
#define LDH       200

__device__ __align__(16) __half g_k[NW*WIN_ELEMS];
__device__ __align__(16) __half g_v[NW*WIN_ELEMS];
__device__ __align__(16) __half g_lepe[NW*WIN_ELEMS];
__device__ __align__(16) __half g_wh[147456];   // fp16 wqkv (110592) then wout (36864)

__device__ __forceinline__ unsigned smem_u32(const void* ptr)
{
    return (unsigned)__cvta_generic_to_shared(ptr);
}

__device__ __forceinline__ void ldsm4(unsigned* r, unsigned a)
{
    asm volatile("ldmatrix.sync.aligned.m8n8.x4.shared.b16 {%0,%1,%2,%3}, [%4];" : "=r"(r[0]), "=r"(r[1]), "=r"(r[2]), "=r"(r[3]) : "r"(a));
}

__device__ __forceinline__ void ldsm4t(unsigned* r, unsigned a)
{
    asm volatile("ldmatrix.sync.aligned.m8n8.x4.trans.shared.b16 {%0,%1,%2,%3}, [%4];" : "=r"(r[0]), "=r"(r[1]), "=r"(r[2]), "=r"(r[3]) : "r"(a));
}

__device__ __forceinline__ void mma16816(float* d, const unsigned* a, const unsigned* b)
{
    asm volatile("mma.sync.aligned.m16n8k16.row.col.f32.f16.f16.f32 {%0,%1,%2,%3},{%4,%5,%6,%7},{%8,%9},{%0,%1,%2,%3};" : "+f"(d[0]), "+f"(d[1]), "+f"(d[2]), "+f"(d[3]) : "r"(a[0]), "r"(a[1]), "r"(a[2]), "r"(a[3]), "r"(b[0]), "r"(b[1]));
}

__device__ __forceinline__ void cpa16(unsigned dst, const void* src)
{
    asm volatile("cp.async.cg.shared.global [%0], [%1], 16;" :: "r"(dst), "l"(src));
}

#define CPA_COMMIT() asm volatile("cp.async.commit_group;")
#define CPA_WAIT(n)  asm volatile("cp.async.wait_group %0;" :: "n"(n))

// ---------------------------------------------------------------------------
// K0: one-shot weight conversion fp32 -> fp16 (wqkv then wout).
// ---------------------------------------------------------------------------
__global__ __launch_bounds__(256) void convw_kernel(const float* __restrict__ wqkv, const float* __restrict__ wout)
{
    int i = blockIdx.x*256 + threadIdx.x;
    if (i < 55296) {
        ((__half2*)g_wh)[i] = __floats2half2_rn(wqkv[2*i], wqkv[2*i+1]);
    } else if (i < 73728) {
        int j = i - 55296;
        ((__half2*)g_wh)[i] = __floats2half2_rn(wout[2*j], wout[2*j+1]);
    }
}

// ---------------------------------------------------------------------------
// K1: K/V projection (HMMA) + fused LePE tail. CTA = half window (128 rows).
// 6 N-tiles of 64 (K then V); Q is computed inside attn now.
// ---------------------------------------------------------------------------
__global__ __launch_bounds__(256) void qkv_kernel(const float* __restrict__ x, const float* __restrict__ bqkv,
                                                  const float* __restrict__ wpe, const float* __restrict__ bpe)
{
    extern __shared__ __half sh_qkv[];
    __half* As    = sh_qkv;
    float*  s_wpe = (float*)((char*)sh_qkv + 102400);
    float*  s_bpe = s_wpe + 864;

    const int tid  = threadIdx.x;
    const int warp = tid >> 5;
    const int lane = tid & 31;
    const int hw   = blockIdx.x;
    const int win  = hw >> 1;
    const int t0   = (hw & 1) * 128;
    const int cbase= (hw & 1) * 96;
    const int bb   = win >> 8;
    const int hy   = (win >> 4) & 15;
    const int wx   = win & 15;
    const int winbase = bb*12582912 + hy*786432 + wx*3072;
    const int grp  = lane >> 2;
    const int t2   = (lane & 3) * 2;
    const int wm   = (warp >> 1) * 32;
    const int wn   = (warp & 1) * 32;

    #pragma unroll
    for (int bt = 0; bt < 2; bt++) {
        const __half* wsrc = g_wh + 36864 + bt*64*192;
        unsigned bbase = smem_u32((char*)sh_qkv + 51200 + bt*25600);
        #pragma unroll
        for (int it = 0; it < 6; it++) {
            int i   = tid + it*256;
            int row = i / 24;
            int cc  = (i % 24) * 8;
            cpa16(bbase + row*(LDH*2) + cc*2, wsrc + row*192 + cc);
        }
        CPA_COMMIT();
    }

    #pragma unroll
    for (int it = 0; it < 4; it++) {
        int i = tid + it*256;
        if (i < 864) { s_wpe[i] = wpe[cbase*9 + i]; }
    }
    if (tid < 96) { s_bpe[tid] = bpe[cbase + tid]; }

    #pragma unroll
    for (int it = 0; it < 24; it++) {
        int i   = tid + it*256;
        int row = i / 48;
        int c   = (i % 48) * 4;
        int gtok = t0 + row;
        const float* src = x + winbase + (gtok>>4)*49152 + (gtok&15)*192 + c;
        float4 av = *(const float4*)src;
        __half2* dp = (__half2*)(As + row*LDH + c);
        dp[0] = __floats2half2_rn(av.x, av.y);
        dp[1] = __floats2half2_rn(av.z, av.w);
    }

    for (int nt = 0; nt < 6; nt++) {
        if (nt >= 4) { CPA_WAIT(0); } else { CPA_WAIT(1); }
        __syncthreads();

        const __half* Bs = (const __half*)((char*)sh_qkv + 51200 + (nt & 1)*25600);

        float acc[2][4][4];
        for (int i = 0; i < 2; i++) {
            for (int j = 0; j < 4; j++) {
                for (int q = 0; q < 4; q++) { acc[i][j][q] = 0.f; }
            }
        }

        #pragma unroll
        for (int k0 = 0; k0 < 192; k0 += 16) {
            unsigned afr[2][4];
            #pragma unroll
            for (int mi = 0; mi < 2; mi++) {
                unsigned aaddr = smem_u32(As + (wm + mi*16 + (lane&15))*LDH + k0 + (lane>>4)*8);
                ldsm4(afr[mi], aaddr);
            }
            #pragma unroll
            for (int nb = 0; nb < 2; nb++) {
                unsigned bfr[4];
                unsigned baddr = smem_u32(Bs + (wn + nb*16 + (lane&7) + ((lane>>4)<<3))*LDH + k0 + ((lane>>3)&1)*8);
                ldsm4(bfr, baddr);
                #pragma unroll
                for (int mi = 0; mi < 2; mi++) {
                    mma16816(acc[mi][nb*2],   afr[mi], bfr);
                    mma16816(acc[mi][nb*2+1], afr[mi], bfr+2);
                }
            }
        }
        __syncthreads();

        if (nt + 2 < 6) {
            const __half* wsrc = g_wh + 36864 + (nt+2)*64*192;
            unsigned bbase = smem_u32((char*)sh_qkv + 51200 + (nt & 1)*25600);
            #pragma unroll
            for (int it = 0; it < 6; it++) {
                int i   = tid + it*256;
                int row = i / 24;
                int cc  = (i % 24) * 8;
                cpa16(bbase + row*(LDH*2) + cc*2, wsrc + row*192 + cc);
            }
        }
        CPA_COMMIT();

        __half* obuf = (nt < 3) ? g_k : g_v;
        const int c0 = (nt % 3) * 64;
        const float* bp = bqkv + 192 + nt*64;

        #pragma unroll
        for (int mi = 0; mi < 2; mi++) {
            #pragma unroll
            for (int rh = 0; rh < 2; rh++) {
                int tok = t0 + wm + mi*16 + grp + rh*8;
                __half* orow = obuf + win*WIN_ELEMS + tok*192 + c0;
                #pragma unroll
                for (int nj = 0; nj < 4; nj++) {
                    int cl = wn + nj*8 + t2;
                    float v0 = acc[mi][nj][rh*2+0] + bp[cl];
                    float v1 = acc[mi][nj][rh*2+1] + bp[cl+1];
                    *(__half2*)(orow + cl) = __floats2half2_rn(v0, v1);
                }
            }
        }
    }

    __syncthreads();
    __half* vflat = As;
    const __half* vsrc = g_v + win*WIN_ELEMS + t0*192;
    #pragma unroll
    for (int it = 0; it < 12; it++) {
        int i = tid + it*256;
        ((uint4*)vflat)[i] = ((const uint4*)vsrc)[i];
    }
    __syncthreads();

    __half* ldst = g_lepe + win*WIN_ELEMS + t0*192;
    #pragma unroll 4
    for (int it = 0; it < 96; it++) {
        int f  = tid + it*256;
        int ci = f >> 8;
        int p  = f & 255;
        int iy = p >> 4;
        int ix = p & 15;
        float s = s_bpe[ci];
        const float* wv = s_wpe + ci*9;
        const __half* img = vflat + ci*256;
        #pragma unroll
        for (int dy = -1; dy <= 1; dy++) {
            #pragma unroll
            for (int dx = -1; dx <= 1; dx++) {
                int jy = iy + dy;
                int jx = ix + dx;
                if (jy >= 0 && jy < 16 && jx >= 0 && jx < 16) {
                    s += __half2float(img[jy*16 + jx]) * wv[(dy+1)*3 + (dx+1)];
                }
            }
        }
        ldst[f] = __float2half(s);
    }
}

// ---------------------------------------------------------------------------
// K3: fused Q-proj + attention + output-proj. 256 threads, 8 warps.
// smem (153600 B), phase-overlaid:
//   phase Q: wq[0,76800)  xs[102400,153600)
//   phase S: Kfull[0,102400)
//   phase PV/proj: Wt[0,76800)  Vbuf0[102400,128000) Vbuf1[128000,153600)
// cp.async: C1=wq  C2=K  C3=V0  C4=V1  C5=Wt  C6=V2  C7=V3
// ---------------------------------------------------------------------------
__global__ __launch_bounds__(256) void attn_kernel(const float* __restrict__ x, const float* __restrict__ bqkv,
                                                   const float* __restrict__ bout, float* __restrict__ out)
{
    extern __shared__ char sh_attn[];
    __half* WqK = (__half*)sh_attn;                 // wq, then Kfull, then Wt
    __half* Xs  = (__half*)(sh_attn + 102400);      // x fp16 [128][LDH]

    const int tid  = threadIdx.x;
    const int warp = tid >> 5;
    const int lane = tid & 31;
    const int win  = blockIdx.x >> 1;
    const int t0   = (blockIdx.x & 1) * 128;
    const int grp  = lane >> 2;
    const int t2   = (lane & 3) * 2;
    const int wm   = warp * 16;

    const int bb = win >> 8;
    const int hy = (win >> 4) & 15;
    const int wx = win & 15;
    const int winbase = bb*12582912 + hy*786432 + wx*3072;

    const __half* kg = g_k + win*WIN_ELEMS;
    const __half* vg = g_v + win*WIN_ELEMS;

    // C1: wq (192 rows x 192) into [0,76800)
    #pragma unroll
    for (int it = 0; it < 18; it++) {
        int i   = tid + it*256;
        int row = i / 24;
        int cc  = (i % 24) * 8;
        cpa16(smem_u32(WqK + row*LDH + cc), g_wh + row*192 + cc);
    }
    CPA_COMMIT();

    // gather x half-window -> fp16 Xs (overlaps C1)
    #pragma unroll
    for (int it = 0; it < 24; it++) {
        int i   = tid + it*256;
        int row = i / 48;
        int c   = (i % 48) * 4;
        int gtok = t0 + row;
        const float* src = x + winbase + (gtok>>4)*49152 + (gtok&15)*192 + c;
        float4 av = *(const float4*)src;
        __half2* dp = (__half2*)(Xs + row*LDH + c);
        dp[0] = __floats2half2_rn(av.x, av.y);
        dp[1] = __floats2half2_rn(av.z, av.w);
    }

    CPA_WAIT(0);
    __syncthreads();

    // ---- Q = x @ wq^T + bq : per-warp 16 rows x 192 cols, all in regs ----
    float qacc[24][4];
    for (int j = 0; j < 24; j++) {
        for (int q = 0; q < 4; q++) { qacc[j][q] = 0.f; }
    }
    #pragma unroll
    for (int ks = 0; ks < 12; ks++) {
        unsigned afr[4];
        unsigned aaddr = smem_u32(Xs + (wm + (lane&15))*LDH + ks*16 + (lane>>4)*8);
        ldsm4(afr, aaddr);
        #pragma unroll
        for (int nj2 = 0; nj2 < 12; nj2++) {
            unsigned bfr[4];
            unsigned baddr = smem_u32(WqK + (nj2*16 + (lane&7) + ((lane>>4)<<3))*LDH + ks*16 + ((lane>>3)&1)*8);
            ldsm4(bfr, baddr);
            mma16816(qacc[nj2*2],   afr, bfr);
            mma16816(qacc[nj2*2+1], afr, bfr+2);
        }
    }

    // bias + pack to S-phase A-fragments
    unsigned qa[48];
    #pragma unroll
    for (int nj = 0; nj < 24; nj++) {
        int c = nj*8 + t2;
        float b0 = bqkv[c];
        float b1 = bqkv[c+1];
        __half2 h01 = __floats2half2_rn(qacc[nj][0] + b0, qacc[nj][1] + b1);
        __half2 h23 = __floats2half2_rn(qacc[nj][2] + b0, qacc[nj][3] + b1);
        qa[nj*2+0] = *(unsigned*)&h01;
        qa[nj*2+1] = *(unsigned*)&h23;
    }
    __syncthreads();   // Xs + wq dead

    // C2: K full (256 rows) into [0,102400)
    #pragma unroll
    for (int it = 0; it < 24; it++) {
        int i   = tid + it*256;
        int row = i / 24;
        int cc  = (i % 24) * 8;
        cpa16(smem_u32(WqK + row*LDH + cc), kg + row*192 + cc);
    }
    CPA_COMMIT();
    // C3, C4: V chunks 0,1
    #pragma unroll
    for (int vc0 = 0; vc0 < 2; vc0++) {
        unsigned vb = smem_u32(sh_attn + 102400 + vc0*25600);
        #pragma unroll
        for (int it = 0; it < 6; it++) {
            int i   = tid + it*256;
            int row = i / 24;
            int cc  = (i % 24) * 8;
            cpa16(vb + row*(LDH*2) + cc*2, vg + (vc0*64+row)*192 + cc);
        }
        CPA_COMMIT();
    }

    CPA_WAIT(2);       // K ready
    __syncthreads();

    // ---- S = Q K^T ----
    float acc[32][4];
    for (int j = 0; j < 32; j++) {
        for (int q = 0; q < 4; q++) { acc[j][q] = 0.f; }
    }
    #pragma unroll
    for (int ks = 0; ks < 12; ks++) {
        #pragma unroll
        for (int njp = 0; njp < 16; njp++) {
            unsigned bfr[4];
            unsigned baddr = smem_u32(WqK + (njp*16 + (lane&7) + ((lane>>4)<<3))*LDH + ks*16 + ((lane>>3)&1)*8);
            ldsm4(bfr, baddr);
            mma16816(acc[njp*2],   qa + ks*4, bfr);
            mma16816(acc[njp*2+1], qa + ks*4, bfr+2);
        }
    }
    __syncthreads();   // K dead

    // C5: Wt into [0,76800)
    #pragma unroll
    for (int it = 0; it < 18; it++) {
        int i   = tid + it*256;
        int row = i / 24;
        int cc  = (i % 24) * 8;
        cpa16(smem_u32(WqK + row*LDH + cc), g_wh + 110592 + row*192 + cc);
    }
    CPA_COMMIT();

    // ---- softmax in registers ----
    const float scale = 0.07216878364870323f;
    float mx0 = -1e30f;
    float mx1 = -1e30f;
    #pragma unroll
    for (int nj = 0; nj < 32; nj++) {
        acc[nj][0] *= scale; acc[nj][1] *= scale;
        acc[nj][2] *= scale; acc[nj][3] *= scale;
        mx0 = fmaxf(mx0, fmaxf(acc[nj][0], acc[nj][1]));
        mx1 = fmaxf(mx1, fmaxf(acc[nj][2], acc[nj][3]));
    }
    mx0 = fmaxf(mx0, __shfl_xor_sync(0xffffffffu, mx0, 1));
    mx0 = fmaxf(mx0, __shfl_xor_sync(0xffffffffu, mx0, 2));
    mx1 = fmaxf(mx1, __shfl_xor_sync(0xffffffffu, mx1, 1));
    mx1 = fmaxf(mx1, __shfl_xor_sync(0xffffffffu, mx1, 2));

    unsigned ph[64];
    float sum0 = 0.f;
    float sum1 = 0.f;
    #pragma unroll
    for (int nj = 0; nj < 32; nj++) {
        float e0 = __expf(acc[nj][0] - mx0);
        float e1 = __expf(acc[nj][1] - mx0);
        float e2 = __expf(acc[nj][2] - mx1);
        float e3 = __expf(acc[nj][3] - mx1);
        sum0 += e0 + e1;
        sum1 += e2 + e3;
        __half2 h01 = __floats2half2_rn(e0, e1);
        __half2 h23 = __floats2half2_rn(e2, e3);
        ph[nj*2+0] = *(unsigned*)&h01;
        ph[nj*2+1] = *(unsigned*)&h23;
    }
    sum0 += __shfl_xor_sync(0xffffffffu, sum0, 1);
    sum0 += __shfl_xor_sync(0xffffffffu, sum0, 2);
    sum1 += __shfl_xor_sync(0xffffffffu, sum1, 1);
    sum1 += __shfl_xor_sync(0xffffffffu, sum1, 2);
    const float inv0 = 1.f / sum0;
    const float inv1 = 1.f / sum1;

    // ---- O = P V : 4 V chunks of 64, double-buffered ----
    float oacc[24][4];
    for (int j = 0; j < 24; j++) {
        for (int q = 0; q < 4; q++) { oacc[j][q] = 0.f; }
    }

    #pragma unroll
    for (int cc4 = 0; cc4 < 4; cc4++) {
        if (cc4 == 0) { CPA_WAIT(2); }
        else if (cc4 == 1) { CPA_WAIT(2); }
        else if (cc4 == 2) { CPA_WAIT(1); }
        else { CPA_WAIT(0); }
        __syncthreads();

        const __half* Vb = (const __half*)(sh_attn + 102400 + (cc4 & 1)*25600);

        #pragma unroll
        for (int kq = 0; kq < 4; kq++) {
            int kt = cc4*4 + kq;
            #pragma unroll
            for (int g12 = 0; g12 < 12; g12++) {
                unsigned bfr[4];
                unsigned baddr = smem_u32(Vb + (kq*16 + (lane&7) + ((lane>>3)&1)*8)*LDH + g12*16 + (lane>>4)*8);
                ldsm4t(bfr, baddr);
                mma16816(oacc[g12*2],   ph + 4*kt, bfr);
                mma16816(oacc[g12*2+1], ph + 4*kt, bfr+2);
            }
        }
        __syncthreads();

        if (cc4 < 2) {
            unsigned vb = smem_u32(sh_attn + 102400 + (cc4 & 1)*25600);
            #pragma unroll
            for (int it = 0; it < 6; it++) {
                int i   = tid + it*256;
                int row = i / 24;
                int cc  = (i % 24) * 8;
                cpa16(vb + row*(LDH*2) + cc*2, vg + ((cc4+2)*64+row)*192 + cc);
            }
            CPA_COMMIT();
        }
    }

    // ---- finalize O: inv + lepe; repack as proj A-fragments ----
    const __half* lw = g_lepe + win*WIN_ELEMS + t0*192;
    unsigned oh[48];
    #pragma unroll
    for (int nj = 0; nj < 24; nj++) {
        int c = nj*8 + t2;
        __half2 l0 = *(const __half2*)(lw + (wm + grp)*192 + c);
        __half2 l1 = *(const __half2*)(lw + (wm + grp + 8)*192 + c);
        float2 lp0 = __half22float2(l0);
        float2 lp1 = __half22float2(l1);
        float v0 = oacc[nj][0]*inv0 + lp0.x;
        float v1 = oacc[nj][1]*inv0 + lp0.y;
        float v2 = oacc[nj][2]*inv1 + lp1.x;
        float v3 = oacc[nj][3]*inv1 + lp1.y;
        __half2 h01 = __floats2half2_rn(v0, v1);
        __half2 h23 = __floats2half2_rn(v2, v3);
        oh[nj*2+0] = *(unsigned*)&h01;
        oh[nj*2+1] = *(unsigned*)&h23;
    }

    // ---- fused projection: O (regs) @ wout (smem Wt), scatter to out ----
    float pacc[24][4];
    for (int j = 0; j < 24; j++) {
        for (int q = 0; q < 4; q++) { pacc[j][q] = 0.f; }
    }
    #pragma unroll
    for (int ks = 0; ks < 12; ks++) {
        #pragma unroll
        for (int nj2 = 0; nj2 < 12; nj2++) {
            unsigned bfr[4];
            unsigned baddr = smem_u32(WqK + (nj2*16 + (lane&7) + ((lane>>4)<<3))*LDH + ks*16 + ((lane>>3)&1)*8);
            ldsm4(bfr, baddr);
            mma16816(pacc[nj2*2],   oh + 4*ks, bfr);
            mma16816(pacc[nj2*2+1], oh + 4*ks, bfr+2);
        }
    }

    #pragma unroll
    for (int rh = 0; rh < 2; rh++) {
        int t  = t0 + wm + grp + rh*8;
        int ty = t >> 4;
        int tx = t & 15;
        int base = bb*12582912 + hy*786432 + ty*49152 + wx*3072 + tx*192;
        #pragma unroll
        for (int nj = 0; nj < 24; nj++) {
            int c = nj*8 + t2;
            float2 o2;
            o2.x = pacc[nj][rh*2+0] + bout[c];
            o2.y = pacc[nj][rh*2+1] + bout[c+1];
            *(float2*)(out + base + c) = o2;
        }
    }
}

// ---------------------------------------------------------------------------
extern "C" void kernel_launch(void* const* d_in, const int* in_sizes, int n_in,
                              void* d_out, int out_size)
{
    const float* x    = (const float*)d_in[0];
    const float* wqkv = (const float*)d_in[1];
    const float* bqkv = (const float*)d_in[2];
    const float* wpe  = (const float*)d_in[3];
    const float* bpe  = (const float*)d_in[4];
    const float* wout = (const float*)d_in[5];
    const float* bout = (const float*)d_in[6];
    float* out = (float*)d_out;

    const int sm_qkv  = 106240;
    const int sm_attn = 153600;
    cudaFuncSetAttribute(qkv_kernel,  cudaFuncAttributeMaxDynamicSharedMemorySize, sm_qkv);
    cudaFuncSetAttribute(attn_kernel, cudaFuncAttributeMaxDynamicSharedMemorySize, sm_attn);

    convw_kernel<<<288, 256>>>(wqkv, wout);
    qkv_kernel <<<2048, 256, sm_qkv>>>(x, bqkv, wpe, bpe);
    attn_kernel<<<2048, 256, sm_attn>>>(x, bqkv, bout, out);
}